// round 5
// baseline (speedup 1.0000x reference)
#include <cuda_runtime.h>

// Problem constants (fixed by setup_inputs):
// x_0  : [128, 64, 16] f32   (d_in[0])
// x_h  : [128, 64, 16] f32   (d_in[1], UNUSED — reference bug recomputes from x_0)
// Vm   : [64, 1, 64, 16] f32 (d_in[2])
// Vh   : [64, 1, 16, 64] f32 (d_in[3])
// out  : [128, 64, 16] f32
//
// out[b,k,d] = sum_v ( sum_i x0[b,i,d]*Vm[k,i,v] ) * ( sum_j x0flat[b,64d+j]*Vh[k,v,j] )

#define NTHR 64
#define KG   4   // k-values per CTA
#define BBLK 8   // batches per CTA

// ---- packed f32x2 helpers (FFMA2 path; ptxas won't fuse from C++) ----
__device__ __forceinline__ unsigned long long pack2(float x) {
    unsigned long long r;
    asm("mov.b64 %0, {%1, %1};" : "=l"(r) : "f"(x));
    return r;
}
__device__ __forceinline__ void fma2(unsigned long long& d,
                                     unsigned long long a,
                                     unsigned long long b) {
    asm("fma.rn.f32x2 %0, %1, %2, %0;" : "+l"(d) : "l"(a), "l"(b));
}
__device__ __forceinline__ void lds_2x64(unsigned long long& p0,
                                         unsigned long long& p1,
                                         unsigned addr) {
    asm("ld.shared.v2.u64 {%0, %1}, [%2];" : "=l"(p0), "=l"(p1) : "r"(addr));
}
__device__ __forceinline__ void unpack2(float& lo, float& hi, unsigned long long p) {
    asm("mov.b64 {%0, %1}, %2;" : "=f"(lo), "=f"(hi) : "l"(p));
}

// Dynamic SMEM layout (floats):
//   Xa  [    0,  8192)  Xa[i*128 + row] = x0[(bbase+row/16)*1024 + i*16 + row%16]
//   Xb  [ 8192, 16384)  Xb[j*128 + row] = x0[(bbase+row/16)*1024 + (row%16)*64 + j]
//   VmS [16384, 20480)  VmS[q*1024 + i*16 + v] = Vm[(k0+q)*1024 + i*16 + v]
//   VhT [20480, 24576)  VhT[q*1024 + j*16 + v] = Vh[(k0+q)*1024 + v*64 + j]
#define SMEM_FLOATS 24576
#define SMEM_BYTES  (SMEM_FLOATS * 4)

__global__ void __launch_bounds__(NTHR)
cin_kernel(const float* __restrict__ x0,
           const float* __restrict__ Vm,
           const float* __restrict__ Vh,
           float* __restrict__ out)
{
    extern __shared__ __align__(16) float smem[];
    float* Xa  = smem;
    float* Xb  = smem + 8192;
    float* VmS = smem + 16384;
    float* VhT = smem + 20480;

    const int tid   = threadIdx.x;
    const int k0    = blockIdx.x * KG;   // 16 k-groups
    const int bbase = blockIdx.y * BBLK; // 16 b-groups

    // ---- stage VmS: 4 consecutive k tiles = 4096 contiguous floats ----
    {
        const float4* src = reinterpret_cast<const float4*>(Vm + k0 * 1024);
        float4* dst = reinterpret_cast<float4*>(VmS);
        #pragma unroll
        for (int r = 0; r < 16; r++) dst[tid + r * NTHR] = src[tid + r * NTHR];
    }
    // ---- stage VhT: transpose Vh[k][v][j] -> VhT[q][j][v] ----
    {
        #pragma unroll 8
        for (int r = 0; r < 64; r++) {
            int idx = tid + r * NTHR;            // 0..4095
            int q   = idx >> 10;
            int rem = idx & 1023;
            int j   = rem >> 4;
            int v   = rem & 15;
            VhT[idx] = Vh[(k0 + q) * 1024 + v * 64 + j];
        }
    }
    // ---- stage Xa: Xa[i*128 + bl*16 + d] = x0[b][i][d] ----
    {
        #pragma unroll 8
        for (int r = 0; r < 128; r++) {
            int idx = tid + r * NTHR;            // 0..8191
            int i   = idx >> 7;
            int row = idx & 127;
            int bl  = row >> 4;
            int d   = row & 15;
            Xa[idx] = x0[(bbase + bl) * 1024 + i * 16 + d];
        }
    }
    // ---- stage Xb: Xb[j*128 + bl*16 + d] = x0flat[b][d*64 + j] (float4 reads) ----
    {
        #pragma unroll 4
        for (int r = 0; r < 32; r++) {
            int idx = tid + r * NTHR;            // 0..2047
            int bl  = idx >> 8;
            int j4  = (idx >> 4) & 15;
            int d   = idx & 15;
            float4 w = *reinterpret_cast<const float4*>(
                x0 + (bbase + bl) * 1024 + d * 64 + j4 * 4);
            int base = (j4 * 4) * 128 + bl * 16 + d;
            Xb[base      ] = w.x;
            Xb[base + 128] = w.y;
            Xb[base + 256] = w.z;
            Xb[base + 384] = w.w;
        }
    }
    __syncthreads();

    const unsigned smem_b = (unsigned)__cvta_generic_to_shared(smem);
    const unsigned vm_b   = smem_b + 16384u * 4u;
    const unsigned vh_b   = smem_b + 20480u * 4u;

    // Each thread owns rows (2t, 2t+1): same bl, adjacent d (d0 even).
    const int row0 = 2 * tid;
    const int bl   = row0 >> 4;
    const int d0   = row0 & 15;
    float* out_ptr = out + (bbase + bl) * 1024 + d0;

    #pragma unroll 1
    for (int q = 0; q < KG; q++) {
        unsigned long long A0[8], A1[8], B0[8], B1[8];
        #pragma unroll
        for (int p = 0; p < 8; p++) { A0[p]=0ull; A1[p]=0ull; B0[p]=0ull; B1[p]=0ull; }

        const unsigned va = vm_b + q * 4096u;
        const unsigned vb = vh_b + q * 4096u;

        // A side: contract over i with Vm
        #pragma unroll 4
        for (int i = 0; i < 64; i++) {
            float2 xa = *reinterpret_cast<const float2*>(&Xa[i * 128 + row0]);
            unsigned long long xp0 = pack2(xa.x);
            unsigned long long xp1 = pack2(xa.y);
            unsigned a = va + (unsigned)(i * 64);
            unsigned long long p0,p1,p2,p3,p4,p5,p6,p7;
            lds_2x64(p0, p1, a);
            lds_2x64(p2, p3, a + 16u);
            lds_2x64(p4, p5, a + 32u);
            lds_2x64(p6, p7, a + 48u);
            fma2(A0[0], xp0, p0); fma2(A1[0], xp1, p0);
            fma2(A0[1], xp0, p1); fma2(A1[1], xp1, p1);
            fma2(A0[2], xp0, p2); fma2(A1[2], xp1, p2);
            fma2(A0[3], xp0, p3); fma2(A1[3], xp1, p3);
            fma2(A0[4], xp0, p4); fma2(A1[4], xp1, p4);
            fma2(A0[5], xp0, p5); fma2(A1[5], xp1, p5);
            fma2(A0[6], xp0, p6); fma2(A1[6], xp1, p6);
            fma2(A0[7], xp0, p7); fma2(A1[7], xp1, p7);
        }
        // B side: contract over j with Vh^T
        #pragma unroll 4
        for (int j = 0; j < 64; j++) {
            float2 xb = *reinterpret_cast<const float2*>(&Xb[j * 128 + row0]);
            unsigned long long xp0 = pack2(xb.x);
            unsigned long long xp1 = pack2(xb.y);
            unsigned a = vb + (unsigned)(j * 64);
            unsigned long long p0,p1,p2,p3,p4,p5,p6,p7;
            lds_2x64(p0, p1, a);
            lds_2x64(p2, p3, a + 16u);
            lds_2x64(p4, p5, a + 32u);
            lds_2x64(p6, p7, a + 48u);
            fma2(B0[0], xp0, p0); fma2(B1[0], xp1, p0);
            fma2(B0[1], xp0, p1); fma2(B1[1], xp1, p1);
            fma2(B0[2], xp0, p2); fma2(B1[2], xp1, p2);
            fma2(B0[3], xp0, p3); fma2(B1[3], xp1, p3);
            fma2(B0[4], xp0, p4); fma2(B1[4], xp1, p4);
            fma2(B0[5], xp0, p5); fma2(B1[5], xp1, p5);
            fma2(B0[6], xp0, p6); fma2(B1[6], xp1, p6);
            fma2(B0[7], xp0, p7); fma2(B1[7], xp1, p7);
        }

        // out = sum_v A[v]*B[v] for both rows
        float r0 = 0.f, r1 = 0.f;
        #pragma unroll
        for (int p = 0; p < 8; p++) {
            float al, ah, bl_, bh;
            unpack2(al, ah, A0[p]); unpack2(bl_, bh, B0[p]);
            r0 = fmaf(al, bl_, r0); r0 = fmaf(ah, bh, r0);
            unpack2(al, ah, A1[p]); unpack2(bl_, bh, B1[p]);
            r1 = fmaf(al, bl_, r1); r1 = fmaf(ah, bh, r1);
        }
        *reinterpret_cast<float2*>(out_ptr + (k0 + q) * 16) = make_float2(r0, r1);
    }
}

extern "C" void kernel_launch(void* const* d_in, const int* in_sizes, int n_in,
                              void* d_out, int out_size) {
    (void)in_sizes; (void)n_in; (void)out_size;
    const float* x0 = (const float*)d_in[0];
    // d_in[1] (x_h) intentionally unused: reference recomputes it from x_0.
    const float* Vm = (const float*)d_in[2];
    const float* Vh = (const float*)d_in[3];
    float* out = (float*)d_out;

    cudaFuncSetAttribute(cin_kernel,
                         cudaFuncAttributeMaxDynamicSharedMemorySize, SMEM_BYTES);

    dim3 grid(64 / KG, 128 / BBLK);  // (16 k-groups, 16 b-groups)
    cin_kernel<<<grid, NTHR, SMEM_BYTES>>>(x0, Vm, Vh, out);
}

// round 6
// speedup vs baseline: 1.0099x; 1.0099x over previous
#include <cuda_runtime.h>

// Problem constants (fixed by setup_inputs):
// x_0  : [128, 64, 16] f32   (d_in[0])
// x_h  : [128, 64, 16] f32   (d_in[1], UNUSED — reference bug recomputes from x_0)
// Vm   : [64, 1, 64, 16] f32 (d_in[2])
// Vh   : [64, 1, 16, 64] f32 (d_in[3])
// out  : [128, 64, 16] f32
//
// out[b,k,d] = sum_v ( sum_i x0[b,i,d]*Vm[k,i,v] ) * ( sum_j x0flat[b,64d+j]*Vh[k,v,j] )

#define NTHR 512
#define KG   4   // k-values per CTA (one per thread via tid>>7)
#define BBLK 8   // batches per CTA (128 output rows)

// ---- packed f32x2 helpers (FFMA2 path; ptxas won't fuse from C++) ----
__device__ __forceinline__ unsigned long long pack2(float x) {
    unsigned long long r;
    asm("mov.b64 %0, {%1, %1};" : "=l"(r) : "f"(x));
    return r;
}
__device__ __forceinline__ void fma2(unsigned long long& d,
                                     unsigned long long a,
                                     unsigned long long b) {
    asm("fma.rn.f32x2 %0, %1, %2, %0;" : "+l"(d) : "l"(a), "l"(b));
}
__device__ __forceinline__ void lds_2x64(unsigned long long& p0,
                                         unsigned long long& p1,
                                         unsigned addr) {
    asm("ld.shared.v2.u64 {%0, %1}, [%2];" : "=l"(p0), "=l"(p1) : "r"(addr));
}
__device__ __forceinline__ void unpack2(float& lo, float& hi, unsigned long long p) {
    asm("mov.b64 {%0, %1}, %2;" : "=f"(lo), "=f"(hi) : "l"(p));
}

// Dynamic SMEM layout (floats):
//   Xa  [    0,  8192)  Xa[i*128 + row] = x0[(bbase+row/16)*1024 + i*16 + row%16]
//   Xb  [ 8192, 16384)  Xb[j*128 + row] = x0[(bbase+row/16)*1024 + (row%16)*64 + j]
//   VmS [16384, 20480)  VmS[q*1024 + i*16 + v] = Vm[(k0+q)*1024 + i*16 + v]
//   VhT [20480, 24576)  VhT[q*1024 + j*16 + v] = Vh[(k0+q)*1024 + v*64 + j]
#define SMEM_FLOATS 24576
#define SMEM_BYTES  (SMEM_FLOATS * 4)

__global__ void __launch_bounds__(NTHR, 2)
cin_kernel(const float* __restrict__ x0,
           const float* __restrict__ Vm,
           const float* __restrict__ Vh,
           float* __restrict__ out)
{
    extern __shared__ __align__(16) float smem[];
    float* Xa  = smem;
    float* Xb  = smem + 8192;
    float* VmS = smem + 16384;
    float* VhT = smem + 20480;

    const int tid   = threadIdx.x;
    const int k0    = blockIdx.x * KG;   // 16 k-groups
    const int bbase = blockIdx.y * BBLK; // 16 b-groups

    // ---- stage VmS: 4 consecutive k tiles = 4096 contiguous floats (1024 float4) ----
    {
        const float4* src = reinterpret_cast<const float4*>(Vm + k0 * 1024);
        float4* dst = reinterpret_cast<float4*>(VmS);
        #pragma unroll
        for (int r = 0; r < 2; r++) dst[tid + r * NTHR] = src[tid + r * NTHR];
    }
    // ---- stage VhT: transpose Vh[k][v][j] -> VhT[q][j][v] ----
    {
        #pragma unroll
        for (int r = 0; r < 8; r++) {
            int idx = tid + r * NTHR;            // 0..4095
            int q   = idx >> 10;
            int rem = idx & 1023;
            int j   = rem >> 4;
            int v   = rem & 15;
            VhT[idx] = Vh[(k0 + q) * 1024 + v * 64 + j];
        }
    }
    // ---- stage Xa: Xa[i*128 + bl*16 + d] = x0[b][i][d] ----
    {
        #pragma unroll
        for (int r = 0; r < 16; r++) {
            int idx = tid + r * NTHR;            // 0..8191
            int i   = idx >> 7;
            int row = idx & 127;
            int bl  = row >> 4;
            int d   = row & 15;
            Xa[idx] = x0[(bbase + bl) * 1024 + i * 16 + d];
        }
    }
    // ---- stage Xb: Xb[j*128 + bl*16 + d] = x0flat[b][d*64 + j] (float4 reads) ----
    {
        #pragma unroll
        for (int r = 0; r < 4; r++) {
            int idx = tid + r * NTHR;            // 0..2047
            int bl  = idx >> 8;
            int j4  = (idx >> 4) & 15;
            int d   = idx & 15;
            float4 w = *reinterpret_cast<const float4*>(
                x0 + (bbase + bl) * 1024 + d * 64 + j4 * 4);
            int base = (j4 * 4) * 128 + bl * 16 + d;
            Xb[base      ] = w.x;
            Xb[base + 128] = w.y;
            Xb[base + 256] = w.z;
            Xb[base + 384] = w.w;
        }
    }
    __syncthreads();

    const unsigned smem_b = (unsigned)__cvta_generic_to_shared(smem);
    const unsigned xa_b   = smem_b;
    const unsigned xb_b   = smem_b + 8192u * 4u;
    const unsigned vm_b   = smem_b + 16384u * 4u;
    const unsigned vh_b   = smem_b + 20480u * 4u;

    // Each thread owns one output row and one k:
    //   row = tid & 127 (bl = row>>4, d = row&15), q = tid >> 7 (0..3).
    // All 32 lanes of a warp share q -> V loads are pure broadcasts.
    const int row = tid & 127;
    const int q   = tid >> 7;
    const int bl  = row >> 4;
    const int d   = row & 15;

    unsigned long long A[8], B[8];
    #pragma unroll
    for (int p = 0; p < 8; p++) { A[p] = 0ull; B[p] = 0ull; }

    const unsigned va  = vm_b + (unsigned)(q * 4096);
    const unsigned vb  = vh_b + (unsigned)(q * 4096);
    const unsigned xar = xa_b + (unsigned)(row * 4);
    const unsigned xbr = xb_b + (unsigned)(row * 4);

    // A side: contract over i with Vm
    #pragma unroll 2
    for (int i = 0; i < 64; i++) {
        float xa;
        asm("ld.shared.f32 %0, [%1];" : "=f"(xa) : "r"(xar + (unsigned)(i * 512)));
        unsigned long long xp = pack2(xa);
        unsigned a = va + (unsigned)(i * 64);
        unsigned long long p0,p1,p2,p3,p4,p5,p6,p7;
        lds_2x64(p0, p1, a);
        lds_2x64(p2, p3, a + 16u);
        lds_2x64(p4, p5, a + 32u);
        lds_2x64(p6, p7, a + 48u);
        fma2(A[0], xp, p0);
        fma2(A[1], xp, p1);
        fma2(A[2], xp, p2);
        fma2(A[3], xp, p3);
        fma2(A[4], xp, p4);
        fma2(A[5], xp, p5);
        fma2(A[6], xp, p6);
        fma2(A[7], xp, p7);
    }
    // B side: contract over j with Vh^T
    #pragma unroll 2
    for (int j = 0; j < 64; j++) {
        float xb;
        asm("ld.shared.f32 %0, [%1];" : "=f"(xb) : "r"(xbr + (unsigned)(j * 512)));
        unsigned long long xp = pack2(xb);
        unsigned a = vb + (unsigned)(j * 64);
        unsigned long long p0,p1,p2,p3,p4,p5,p6,p7;
        lds_2x64(p0, p1, a);
        lds_2x64(p2, p3, a + 16u);
        lds_2x64(p4, p5, a + 32u);
        lds_2x64(p6, p7, a + 48u);
        fma2(B[0], xp, p0);
        fma2(B[1], xp, p1);
        fma2(B[2], xp, p2);
        fma2(B[3], xp, p3);
        fma2(B[4], xp, p4);
        fma2(B[5], xp, p5);
        fma2(B[6], xp, p6);
        fma2(B[7], xp, p7);
    }

    // out = sum_v A[v]*B[v]
    float r0 = 0.f, r1 = 0.f;
    #pragma unroll
    for (int p = 0; p < 8; p++) {
        float al, ah, blo, bhi;
        unpack2(al, ah, A[p]);
        unpack2(blo, bhi, B[p]);
        r0 = fmaf(al, blo, r0);
        r1 = fmaf(ah, bhi, r1);
    }
    out[(bbase + bl) * 1024 + (k0 + q) * 16 + d] = r0 + r1;
}

extern "C" void kernel_launch(void* const* d_in, const int* in_sizes, int n_in,
                              void* d_out, int out_size) {
    (void)in_sizes; (void)n_in; (void)out_size;
    const float* x0 = (const float*)d_in[0];
    // d_in[1] (x_h) intentionally unused: reference recomputes it from x_0.
    const float* Vm = (const float*)d_in[2];
    const float* Vh = (const float*)d_in[3];
    float* out = (float*)d_out;

    cudaFuncSetAttribute(cin_kernel,
                         cudaFuncAttributeMaxDynamicSharedMemorySize, SMEM_BYTES);

    dim3 grid(64 / KG, 128 / BBLK);  // (16 k-groups, 16 b-groups) = 256 CTAs
    cin_kernel<<<grid, NTHR, SMEM_BYTES>>>(x0, Vm, Vh, out);
}

// round 7
// speedup vs baseline: 1.4009x; 1.3872x over previous
#include <cuda_runtime.h>

// Problem constants (fixed by setup_inputs):
// x_0  : [128, 64, 16] f32   (d_in[0])
// x_h  : [128, 64, 16] f32   (d_in[1], UNUSED — reference bug recomputes from x_0)
// Vm   : [64, 1, 64, 16] f32 (d_in[2])
// Vh   : [64, 1, 16, 64] f32 (d_in[3])
// out  : [128, 64, 16] f32
//
// out[b,k,d] = sum_v ( sum_i x0[b,i,d]*Vm[k,i,v] ) * ( sum_j x0flat[b,64d+j]*Vh[k,v,j] )
//
// Work split: warp = one k; lane = (r,h): rows 8r..8r+7, v-half h (v in [8h,8h+8)).
// 64B of shared-register writeback per FFMA2 -> crossbar and FMA pipe balanced.

#define NTHR 128
#define KG   4   // k per CTA = warps per CTA
#define BBLK 8   // batches per CTA (128 output rows)

// ---- packed f32x2 helpers ----
__device__ __forceinline__ unsigned long long pack2(float x) {
    unsigned long long r;
    asm("mov.b64 %0, {%1, %1};" : "=l"(r) : "f"(x));
    return r;
}
__device__ __forceinline__ void fma2(unsigned long long& d,
                                     unsigned long long a,
                                     unsigned long long b) {
    asm("fma.rn.f32x2 %0, %1, %2, %0;" : "+l"(d) : "l"(a), "l"(b));
}
__device__ __forceinline__ void mul2(unsigned long long& d,
                                     unsigned long long a,
                                     unsigned long long b) {
    asm("mul.rn.f32x2 %0, %1, %2;" : "=l"(d) : "l"(a), "l"(b));
}
__device__ __forceinline__ void lds_2x64(unsigned long long& p0,
                                         unsigned long long& p1,
                                         unsigned addr) {
    asm("ld.shared.v2.u64 {%0, %1}, [%2];" : "=l"(p0), "=l"(p1) : "r"(addr));
}
__device__ __forceinline__ void lds_f4(float& a, float& b, float& c, float& d,
                                       unsigned addr) {
    asm("ld.shared.v4.f32 {%0, %1, %2, %3}, [%4];"
        : "=f"(a), "=f"(b), "=f"(c), "=f"(d) : "r"(addr));
}
__device__ __forceinline__ void unpack2(float& lo, float& hi, unsigned long long p) {
    asm("mov.b64 {%0, %1}, %2;" : "=f"(lo), "=f"(hi) : "l"(p));
}

// Dynamic SMEM layout (floats):
//   Xa  [    0,  8192)  Xa[i*128 + row] = x0[(bbase+row/16)*1024 + i*16 + row%16]
//   Xb  [ 8192, 16384)  Xb[j*128 + row] = x0[(bbase+row/16)*1024 + (row%16)*64 + j]
//   VmS [16384, 20480)  VmS[q*1024 + i*16 + v] = Vm[(k0+q)*1024 + i*16 + v]
//   VhT [20480, 24576)  VhT[q*1024 + j*16 + v] = Vh[(k0+q)*1024 + v*64 + j]
#define SMEM_FLOATS 24576
#define SMEM_BYTES  (SMEM_FLOATS * 4)

__global__ void __launch_bounds__(NTHR, 2)
cin_kernel(const float* __restrict__ x0,
           const float* __restrict__ Vm,
           const float* __restrict__ Vh,
           float* __restrict__ out)
{
    extern __shared__ __align__(16) float smem[];
    float* Xa  = smem;
    float* Xb  = smem + 8192;
    float* VmS = smem + 16384;
    float* VhT = smem + 20480;

    const int tid   = threadIdx.x;
    const int k0    = blockIdx.x * KG;   // 16 k-groups
    const int bbase = blockIdx.y * BBLK; // 16 b-groups

    // ---- stage VmS: 4 consecutive k tiles = 4096 contiguous floats ----
    {
        const float4* src = reinterpret_cast<const float4*>(Vm + k0 * 1024);
        float4* dst = reinterpret_cast<float4*>(VmS);
        #pragma unroll
        for (int r = 0; r < 8; r++) dst[tid + r * NTHR] = src[tid + r * NTHR];
    }
    // ---- stage VhT: transpose Vh[k][v][j] -> VhT[q][j][v] ----
    {
        #pragma unroll
        for (int r = 0; r < 32; r++) {
            int idx = tid + r * NTHR;            // 0..4095
            int q   = idx >> 10;
            int rem = idx & 1023;
            int j   = rem >> 4;
            int v   = rem & 15;
            VhT[idx] = Vh[(k0 + q) * 1024 + v * 64 + j];
        }
    }
    // ---- stage Xa: Xa[i*128 + bl*16 + d] = x0[b][i][d]  (float4 both sides) ----
    {
        #pragma unroll
        for (int r = 0; r < 16; r++) {
            int idx = tid + r * NTHR;            // 0..2047 float4s
            int d4  = idx & 3;
            int bl  = (idx >> 2) & 7;
            int i   = idx >> 5;
            float4 w = *reinterpret_cast<const float4*>(
                x0 + (bbase + bl) * 1024 + i * 16 + d4 * 4);
            *reinterpret_cast<float4*>(&Xa[i * 128 + bl * 16 + d4 * 4]) = w;
        }
    }
    // ---- stage Xb: Xb[j*128 + bl*16 + d] = x0flat[b][d*64 + j] (float4 reads) ----
    {
        #pragma unroll
        for (int r = 0; r < 16; r++) {
            int idx = tid + r * NTHR;            // 0..2047
            int bl  = idx >> 8;
            int j4  = (idx >> 4) & 15;
            int d   = idx & 15;
            float4 w = *reinterpret_cast<const float4*>(
                x0 + (bbase + bl) * 1024 + d * 64 + j4 * 4);
            int base = (j4 * 4) * 128 + bl * 16 + d;
            Xb[base      ] = w.x;
            Xb[base + 128] = w.y;
            Xb[base + 256] = w.z;
            Xb[base + 384] = w.w;
        }
    }
    __syncthreads();

    const unsigned smem_b = (unsigned)__cvta_generic_to_shared(smem);
    const unsigned xa_b   = smem_b;
    const unsigned xb_b   = smem_b + 8192u * 4u;
    const unsigned vm_b   = smem_b + 16384u * 4u;
    const unsigned vh_b   = smem_b + 20480u * 4u;

    // warp q -> k = k0+q; lane: r = lane>>1 (row group), h = lane&1 (v-half)
    const int q    = tid >> 5;
    const int lane = tid & 31;
    const int r    = lane >> 1;
    const int h    = lane & 1;

    const unsigned xar = xa_b + (unsigned)(r * 32);                 // 8 rows * 4B
    const unsigned xbr = xb_b + (unsigned)(r * 32);
    const unsigned va  = vm_b + (unsigned)(q * 4096 + h * 32);      // v-half
    const unsigned vb  = vh_b + (unsigned)(q * 4096 + h * 32);

    unsigned long long A[8][4], B[8][4];
    #pragma unroll
    for (int t = 0; t < 8; t++)
        #pragma unroll
        for (int p = 0; p < 4; p++) { A[t][p] = 0ull; B[t][p] = 0ull; }

    // ---- A side: contract over i with Vm ----
    #pragma unroll 2
    for (int i = 0; i < 64; i++) {
        float x[8];
        unsigned xaddr = xar + (unsigned)(i * 512);
        lds_f4(x[0], x[1], x[2], x[3], xaddr);
        lds_f4(x[4], x[5], x[6], x[7], xaddr + 16u);
        unsigned long long p0, p1, p2, p3;
        unsigned vaddr = va + (unsigned)(i * 64);
        lds_2x64(p0, p1, vaddr);
        lds_2x64(p2, p3, vaddr + 16u);
        #pragma unroll
        for (int t = 0; t < 8; t++) {
            unsigned long long xp = pack2(x[t]);
            fma2(A[t][0], xp, p0);
            fma2(A[t][1], xp, p1);
            fma2(A[t][2], xp, p2);
            fma2(A[t][3], xp, p3);
        }
    }
    // ---- B side: contract over j with Vh^T ----
    #pragma unroll 2
    for (int j = 0; j < 64; j++) {
        float x[8];
        unsigned xaddr = xbr + (unsigned)(j * 512);
        lds_f4(x[0], x[1], x[2], x[3], xaddr);
        lds_f4(x[4], x[5], x[6], x[7], xaddr + 16u);
        unsigned long long p0, p1, p2, p3;
        unsigned vaddr = vb + (unsigned)(j * 64);
        lds_2x64(p0, p1, vaddr);
        lds_2x64(p2, p3, vaddr + 16u);
        #pragma unroll
        for (int t = 0; t < 8; t++) {
            unsigned long long xp = pack2(x[t]);
            fma2(B[t][0], xp, p0);
            fma2(B[t][1], xp, p1);
            fma2(B[t][2], xp, p2);
            fma2(B[t][3], xp, p3);
        }
    }

    // ---- dot over this lane's v-half, then combine halves via shfl ----
    float ov[8];
    #pragma unroll
    for (int t = 0; t < 8; t++) {
        unsigned long long P;
        mul2(P, A[t][0], B[t][0]);
        fma2(P, A[t][1], B[t][1]);
        fma2(P, A[t][2], B[t][2]);
        fma2(P, A[t][3], B[t][3]);
        float lo, hi;
        unpack2(lo, hi, P);
        ov[t] = lo + hi;
    }
    #pragma unroll
    for (int t = 0; t < 8; t++)
        ov[t] += __shfl_xor_sync(0xffffffffu, ov[t], 1);

    if (h == 0) {
        // rows 8r..8r+7: bl = r>>1, d0 = (r&1)*8 -> two float4 stores
        float* o = out + (bbase + (r >> 1)) * 1024 + (k0 + q) * 16 + (r & 1) * 8;
        *reinterpret_cast<float4*>(o)     = make_float4(ov[0], ov[1], ov[2], ov[3]);
        *reinterpret_cast<float4*>(o + 4) = make_float4(ov[4], ov[5], ov[6], ov[7]);
    }
}

extern "C" void kernel_launch(void* const* d_in, const int* in_sizes, int n_in,
                              void* d_out, int out_size) {
    (void)in_sizes; (void)n_in; (void)out_size;
    const float* x0 = (const float*)d_in[0];
    // d_in[1] (x_h) intentionally unused: reference recomputes it from x_0.
    const float* Vm = (const float*)d_in[2];
    const float* Vh = (const float*)d_in[3];
    float* out = (float*)d_out;

    cudaFuncSetAttribute(cin_kernel,
                         cudaFuncAttributeMaxDynamicSharedMemorySize, SMEM_BYTES);

    dim3 grid(64 / KG, 128 / BBLK);  // (16 k-groups, 16 b-groups) = 256 CTAs
    cin_kernel<<<grid, NTHR, SMEM_BYTES>>>(x0, Vm, Vh, out);
}